// round 15
// baseline (speedup 1.0000x reference)
#include <cuda_runtime.h>

#define GR 16
#define NCELL 256
#define FR 481                 // fine table nodes/side; 480 = 15*32 -> coarse kinks on nodes

__device__ float4 g_table[FR * FR];   // 3.7 MB, L2-resident

// ---------------- MUFU math ----------------
__device__ __forceinline__ float mufu_ex2(float x) {
    float r; asm("ex2.approx.ftz.f32 %0, %1;" : "=f"(r) : "f"(x)); return r;
}
__device__ __forceinline__ float mufu_rcp(float x) {
    float r; asm("rcp.approx.ftz.f32 %0, %1;" : "=f"(r) : "f"(x)); return r;
}
__device__ __forceinline__ float mufu_rsqrt(float x) {
    float r; asm("rsqrt.approx.ftz.f32 %0, %1;" : "=f"(r) : "f"(x)); return r;
}
__device__ __forceinline__ float silu1(float x) {
    float t = mufu_ex2(x * -1.4426950408889634f);
    return x * mufu_rcp(1.0f + t);
}

// fp32 layernorm + FiLM: h = A*norm + B  (A = gamma*ln_w, B = gamma*ln_b + beta)
__device__ __forceinline__ void lnmod(float* h, const float* A, const float* B) {
    float mu = (h[0] + h[1] + h[2] + h[3] + h[4] + h[5]) * (1.0f / 6.0f);
    float c[6], ss = 0.0f;
#pragma unroll
    for (int i = 0; i < 6; i++) { c[i] = h[i] - mu; ss = fmaf(c[i], c[i], ss); }
    float r = mufu_rsqrt(fmaf(ss, 1.0f / 6.0f, 1e-5f));
#pragma unroll
    for (int i = 0; i < 6; i++) h[i] = fmaf(A[i], c[i] * r, B[i]);
}

// ---------------- prep: evaluate the full network at 481x481 nodes (fp32) ----------------
__global__ __launch_bounds__(256)
void build_table(const float* __restrict__ gamma, const float* __restrict__ beta,
                 const float* __restrict__ lnw,  const float* __restrict__ lnb,
                 const float* __restrict__ w_in, const float* __restrict__ b_in,
                 const float* __restrict__ w_h,  const float* __restrict__ b_h,
                 const float* __restrict__ w_out,const float* __restrict__ b_out) {
    __shared__ float sg[NCELL * 24];   // per cell: l*12 + [A:0..5 | B:6..11], fp32
    __shared__ float sw[81];
    int t = threadIdx.x;

    // fold LN affine into grids (each thread one cell)
    {
        int cell = t;   // blockDim = 256 = NCELL
#pragma unroll
        for (int l = 0; l < 2; l++)
#pragma unroll
            for (int c = 0; c < 6; c++) {
                float g  = gamma[(l * 6 + c) * NCELL + cell];
                float bb = beta[(l * 6 + c) * NCELL + cell];
                sg[cell * 24 + l * 12 + c]     = g * lnw[l * 6 + c];
                sg[cell * 24 + l * 12 + 6 + c] = fmaf(g, lnb[l * 6 + c], bb);
            }
    }
    if (t < 81) {
        float val;
        if      (t < 12) val = w_in[t];
        else if (t < 18) val = b_in[t - 12];
        else if (t < 54) val = w_h[t - 18];
        else if (t < 60) val = b_h[t - 54];
        else if (t < 78) val = w_out[t - 60];
        else             val = b_out[t - 78];
        sw[t] = val;
    }
    __syncthreads();

    int node = blockIdx.x * blockDim.x + t;
    if (node >= FR * FR) return;
    int iy = node / FR, ix = node - iy * FR;
    float x = -1.0f + ix * (2.0f / 480.0f);
    float y = -1.0f + iy * (2.0f / 480.0f);

    // coarse-grid coords: fxc = ix/32 exactly; kinks land on fine nodes
    int cx0 = min(ix >> 5, 15), cy0 = min(iy >> 5, 15);
    float wx = (ix & 31) * (1.0f / 32.0f);
    float wy = (iy & 31) * (1.0f / 32.0f);
    if (ix == 480) wx = 0.0f;
    if (iy == 480) wy = 0.0f;
    int cx1 = min(cx0 + 1, 15), cy1 = min(cy0 + 1, 15);
    const float* c00 = &sg[((cy0 << 4) + cx0) * 24];
    const float* c01 = &sg[((cy0 << 4) + cx1) * 24];
    const float* c10 = &sg[((cy1 << 4) + cx0) * 24];
    const float* c11 = &sg[((cy1 << 4) + cx1) * 24];
    float w11 = wx * wy, w01 = wx - w11, w10 = wy - w11, w00 = 1.0f - wx - wy + w11;

    float AB[24];
#pragma unroll
    for (int k = 0; k < 24; k++)
        AB[k] = fmaf(w00, c00[k], fmaf(w01, c01[k], fmaf(w10, c10[k], w11 * c11[k])));

    // input layer
    float h[6];
#pragma unroll
    for (int c = 0; c < 6; c++)
        h[c] = silu1(fmaf(sw[2 * c], x, fmaf(sw[2 * c + 1], y, sw[12 + c])));

    lnmod(h, &AB[0], &AB[6]);          // layer 0

    // hidden layer
    {
        float nh[6];
#pragma unroll
        for (int c = 0; c < 6; c++) {
            float a = sw[54 + c];
#pragma unroll
            for (int k = 0; k < 6; k++) a = fmaf(sw[18 + c * 6 + k], h[k], a);
            nh[c] = silu1(a);
        }
#pragma unroll
        for (int c = 0; c < 6; c++) h[c] = nh[c];
    }

    lnmod(h, &AB[12], &AB[18]);        // layer 1

    float o[3];
#pragma unroll
    for (int j = 0; j < 3; j++) {
        float a = sw[78 + j];
#pragma unroll
        for (int k = 0; k < 6; k++) a = fmaf(sw[60 + j * 6 + k], h[k], a);
        o[j] = a;
    }
    g_table[node] = make_float4(o[0], o[1], o[2], 0.0f);
}

// ---------------- main: pure bilinear interpolation of the table ----------------
__device__ __forceinline__ void interp_pt(float px, float py,
                                          float& o0, float& o1, float& o2) {
    float fx = fminf(fmaxf(fmaf(px, 240.0f, 240.0f), 0.0f), 480.0f);
    float fy = fminf(fmaxf(fmaf(py, 240.0f, 240.0f), 0.0f), 480.0f);
    float x0f = floorf(fx), y0f = floorf(fy);
    float wx = fx - x0f, wy = fy - y0f;
    int x0 = (int)x0f, y0 = (int)y0f;
    int x1 = min(x0 + 1, FR - 1), y1 = min(y0 + 1, FR - 1);
    int r0 = y0 * FR, r1 = y1 * FR;
    float4 f00 = __ldg(g_table + r0 + x0);
    float4 f01 = __ldg(g_table + r0 + x1);
    float4 f10 = __ldg(g_table + r1 + x0);
    float4 f11 = __ldg(g_table + r1 + x1);
    float w11 = wx * wy, w01 = wx - w11, w10 = wy - w11, w00 = 1.0f - wx - wy + w11;
    o0 = fmaf(w00, f00.x, fmaf(w01, f01.x, fmaf(w10, f10.x, w11 * f11.x)));
    o1 = fmaf(w00, f00.y, fmaf(w01, f01.y, fmaf(w10, f10.y, w11 * f11.y)));
    o2 = fmaf(w00, f00.z, fmaf(w01, f01.z, fmaf(w10, f10.z, w11 * f11.z)));
}

__global__ __launch_bounds__(256)
void interp_kernel(const float4* __restrict__ xy2, float2* __restrict__ out2, int npair) {
    int i = blockIdx.x * blockDim.x + threadIdx.x;
    if (i >= npair) return;
    float4 pp = xy2[i];                 // points 2i, 2i+1 -> high MLP (8 loads in flight)
    float a0, a1, a2, b0, b1, b2;
    interp_pt(pp.x, pp.y, a0, a1, a2);
    interp_pt(pp.z, pp.w, b0, b1, b2);
    out2[3 * i + 0] = make_float2(a0, a1);
    out2[3 * i + 1] = make_float2(a2, b0);
    out2[3 * i + 2] = make_float2(b1, b2);
}

extern "C" void kernel_launch(void* const* d_in, const int* in_sizes, int n_in,
                              void* d_out, int out_size) {
    const float* xy    = (const float*)d_in[0];
    const float* gamma = (const float*)d_in[1];
    const float* beta  = (const float*)d_in[2];
    const float* w_in  = (const float*)d_in[3];
    const float* b_in  = (const float*)d_in[4];
    const float* w_h   = (const float*)d_in[5];
    const float* b_h   = (const float*)d_in[6];
    const float* w_out = (const float*)d_in[7];
    const float* b_out = (const float*)d_in[8];
    const float* ln_w  = (const float*)d_in[9];
    const float* ln_b  = (const float*)d_in[10];
    float* out = (float*)d_out;
    int n = in_sizes[0] / 2;
    int npair = n / 2;                      // N_POINTS is even

    int prep_blocks = (FR * FR + 255) / 256;          // 905
    build_table<<<prep_blocks, 256>>>(gamma, beta, ln_w, ln_b,
                                      w_in, b_in, w_h, b_h, w_out, b_out);

    int main_blocks = (npair + 255) / 256;            // 4096
    interp_kernel<<<main_blocks, 256>>>((const float4*)xy, (float2*)out, npair);
}

// round 17
// speedup vs baseline: 1.5432x; 1.5432x over previous
#include <cuda_runtime.h>
#include <cuda_fp16.h>

#define GR 16
#define NCELL 256
#define FCELL 600              // fine cells/side = 15 coarse intervals * 40
#define FNODE 601

// cell-packed table: 2 uint4 per cell (32B, 32B-aligned):
//  u4A = { f00.x, f00.y, f00.z, half2(d01.x,d01.y) }
//  u4B = { half2(d01.z,d10.x), half2(d10.y,d10.z), half2(d11.x,d11.y), half2(d11.z,0) }
// where d01 = f(x+1,y)-f00, d10 = f(x,y+1)-f00, d11 = f(x+1,y+1)-f00
__device__ uint4 g_cells[FCELL * FCELL * 2];   // 11.5 MB, L2-resident

// ---------------- MUFU math ----------------
__device__ __forceinline__ float mufu_ex2(float x) {
    float r; asm("ex2.approx.ftz.f32 %0, %1;" : "=f"(r) : "f"(x)); return r;
}
__device__ __forceinline__ float mufu_rcp(float x) {
    float r; asm("rcp.approx.ftz.f32 %0, %1;" : "=f"(r) : "f"(x)); return r;
}
__device__ __forceinline__ float mufu_rsqrt(float x) {
    float r; asm("rsqrt.approx.ftz.f32 %0, %1;" : "=f"(r) : "f"(x)); return r;
}
__device__ __forceinline__ float silu1(float x) {
    float t = mufu_ex2(x * -1.4426950408889634f);
    return x * mufu_rcp(1.0f + t);
}

// fp32 layernorm + FiLM: h = A*norm + B
__device__ __forceinline__ void lnmod(float* h, const float* A, const float* B) {
    float mu = (h[0] + h[1] + h[2] + h[3] + h[4] + h[5]) * (1.0f / 6.0f);
    float c[6], ss = 0.0f;
#pragma unroll
    for (int i = 0; i < 6; i++) { c[i] = h[i] - mu; ss = fmaf(c[i], c[i], ss); }
    float r = mufu_rsqrt(fmaf(ss, 1.0f / 6.0f, 1e-5f));
#pragma unroll
    for (int i = 0; i < 6; i++) h[i] = fmaf(A[i], c[i] * r, B[i]);
}

__device__ __forceinline__ unsigned packh2(float a, float b) {
    __half2 h = __floats2half2_rn(a, b);
    return *reinterpret_cast<unsigned*>(&h);
}

// ---------------- prep: tiled eval (16x16 nodes -> 15x15 cells per block) ----------------
// grid = 40x40 blocks (blockIdx.x = by*40+bx), 256 threads.
__global__ __launch_bounds__(256)
void build_cells(const float* __restrict__ gamma, const float* __restrict__ beta,
                 const float* __restrict__ lnw,  const float* __restrict__ lnb,
                 const float* __restrict__ w_in, const float* __restrict__ b_in,
                 const float* __restrict__ w_h,  const float* __restrict__ b_h,
                 const float* __restrict__ w_out,const float* __restrict__ b_out) {
    __shared__ float sgw[9 * 24];     // 3x3 coarse-node window: per node l*12 + isB*6 + c
    __shared__ float sw[81];
    __shared__ float sn[16 * 16 * 3]; // node eval results

    int t = threadIdx.x;
    int bx = blockIdx.x % 40, by = blockIdx.x / 40;
    int cxmin = (15 * bx) / 40;       // coarse window base (cols)
    int cymin = (15 * by) / 40;

    // load 3x3 coarse window, folding LN affine: A = g*lnw, B = beta + g*lnb
    if (t < 216) {
        int wnode = t / 24, k = t - wnode * 24;
        int wrow = wnode / 3, wcol = wnode - wrow * 3;
        int cy = min(cymin + wrow, GR - 1);
        int cx = min(cxmin + wcol, GR - 1);
        int l = k / 12, jj = k - l * 12;
        int isB = jj / 6, c = jj - isB * 6;
        int gi = (l * 6 + c) * NCELL + (cy << 4) + cx;
        float g = gamma[gi];
        float v = isB ? fmaf(g, lnb[l * 6 + c], beta[gi]) : g * lnw[l * 6 + c];
        sgw[t] = v;
    }
    // INDEPENDENT predicate (NOT else-if): 216+81 > 256 would leave sw[40..] unwritten
    if (t < 81) {
        int w = t;
        float val;
        if      (w < 12) val = w_in[w];
        else if (w < 18) val = b_in[w - 12];
        else if (w < 54) val = w_h[w - 18];
        else if (w < 60) val = b_h[w - 54];
        else if (w < 78) val = w_out[w - 60];
        else             val = b_out[w - 78];
        sw[w] = val;
    }
    __syncthreads();

    // evaluate one node per thread
    int lx = t & 15, ly = t >> 4;
    int ix = bx * 15 + lx;            // 0..600
    int iy = by * 15 + ly;
    {
        float x = fmaf((float)ix, 2.0f / 600.0f, -1.0f);
        float y = fmaf((float)iy, 2.0f / 600.0f, -1.0f);

        // coarse interp from window (40 fine intervals per coarse interval)
        int cx0 = min(ix / 40, GR - 1), cy0 = min(iy / 40, GR - 1);
        float wx = (ix - cx0 * 40) * (1.0f / 40.0f);
        float wy = (iy - cy0 * 40) * (1.0f / 40.0f);
        int l00 = (cy0 - cymin) * 3 + (cx0 - cxmin);
        const float* n00 = &sgw[l00 * 24];
        const float* n01 = &sgw[(l00 + 1) * 24];        // window clamp handles edges
        const float* n10 = &sgw[(l00 + 3) * 24];
        const float* n11 = &sgw[(l00 + 4) * 24];
        float w11 = wx * wy, w01 = wx - w11, w10 = wy - w11, w00 = 1.0f - wx - wy + w11;

        float AB[24];
#pragma unroll
        for (int k = 0; k < 24; k++)
            AB[k] = fmaf(w00, n00[k], fmaf(w01, n01[k], fmaf(w10, n10[k], w11 * n11[k])));

        float h[6];
#pragma unroll
        for (int c = 0; c < 6; c++)
            h[c] = silu1(fmaf(sw[2 * c], x, fmaf(sw[2 * c + 1], y, sw[12 + c])));

        lnmod(h, &AB[0], &AB[6]);                       // layer 0 (A,B)

        {
            float nh[6];
#pragma unroll
            for (int c = 0; c < 6; c++) {
                float a = sw[54 + c];
#pragma unroll
                for (int k = 0; k < 6; k++) a = fmaf(sw[18 + c * 6 + k], h[k], a);
                nh[c] = silu1(a);
            }
#pragma unroll
            for (int c = 0; c < 6; c++) h[c] = nh[c];
        }

        lnmod(h, &AB[12], &AB[18]);                     // layer 1

#pragma unroll
        for (int j = 0; j < 3; j++) {
            float a = sw[78 + j];
#pragma unroll
            for (int k = 0; k < 6; k++) a = fmaf(sw[60 + j * 6 + k], h[k], a);
            sn[(ly * 16 + lx) * 3 + j] = a;
        }
    }
    __syncthreads();

    // pack 15x15 cells (threads with lx<15, ly<15)
    if (lx < 15 && ly < 15) {
        const float* f00 = &sn[(ly * 16 + lx) * 3];
        const float* f01 = &sn[(ly * 16 + lx + 1) * 3];
        const float* f10 = &sn[((ly + 1) * 16 + lx) * 3];
        const float* f11 = &sn[((ly + 1) * 16 + lx + 1) * 3];
        float d01x = f01[0] - f00[0], d01y = f01[1] - f00[1], d01z = f01[2] - f00[2];
        float d10x = f10[0] - f00[0], d10y = f10[1] - f00[1], d10z = f10[2] - f00[2];
        float d11x = f11[0] - f00[0], d11y = f11[1] - f00[1], d11z = f11[2] - f00[2];
        uint4 A = make_uint4(__float_as_uint(f00[0]), __float_as_uint(f00[1]),
                             __float_as_uint(f00[2]), packh2(d01x, d01y));
        uint4 B = make_uint4(packh2(d01z, d10x), packh2(d10y, d10z),
                             packh2(d11x, d11y), packh2(d11z, 0.0f));
        int cell = (by * 15 + ly) * FCELL + (bx * 15 + lx);
        g_cells[cell * 2 + 0] = A;
        g_cells[cell * 2 + 1] = B;
    }
}

// ---------------- main: one 32B cell record per point ----------------
__device__ __forceinline__ void interp_pt(float px, float py,
                                          float& o0, float& o1, float& o2) {
    float fx = fminf(fmaxf(fmaf(px, 300.0f, 300.0f), 0.0f), 600.0f);
    float fy = fminf(fmaxf(fmaf(py, 300.0f, 300.0f), 0.0f), 600.0f);
    int x0 = min((int)fx, FCELL - 1);
    int y0 = min((int)fy, FCELL - 1);
    float wx = fx - (float)x0;        // in [0,1]; wx==1 exact at right edge
    float wy = fy - (float)y0;
    int cell = y0 * FCELL + x0;
    uint4 A = __ldg(&g_cells[cell * 2 + 0]);
    uint4 B = __ldg(&g_cells[cell * 2 + 1]);

    float w11 = wx * wy;
    float w01 = wx - w11;             // wx*(1-wy)
    float w10 = wy - w11;             // (1-wx)*wy

    float2 p0 = __half22float2(*reinterpret_cast<__half2*>(&A.w));   // d01.x d01.y
    float2 p1 = __half22float2(*reinterpret_cast<__half2*>(&B.x));   // d01.z d10.x
    float2 p2 = __half22float2(*reinterpret_cast<__half2*>(&B.y));   // d10.y d10.z
    float2 p3 = __half22float2(*reinterpret_cast<__half2*>(&B.z));   // d11.x d11.y
    float2 p4 = __half22float2(*reinterpret_cast<__half2*>(&B.w));   // d11.z --

    o0 = __uint_as_float(A.x);
    o1 = __uint_as_float(A.y);
    o2 = __uint_as_float(A.z);
    o0 = fmaf(w01, p0.x, o0); o0 = fmaf(w10, p1.y, o0); o0 = fmaf(w11, p3.x, o0);
    o1 = fmaf(w01, p0.y, o1); o1 = fmaf(w10, p2.x, o1); o1 = fmaf(w11, p3.y, o1);
    o2 = fmaf(w01, p1.x, o2); o2 = fmaf(w10, p2.y, o2); o2 = fmaf(w11, p4.x, o2);
}

__global__ __launch_bounds__(256)
void interp_kernel(const float4* __restrict__ xy2, float2* __restrict__ out2, int npair) {
    int i = blockIdx.x * blockDim.x + threadIdx.x;
    if (i >= npair) return;
    float4 pp = xy2[i];               // points 2i, 2i+1 (4 table loads in flight)
    float a0, a1, a2, b0, b1, b2;
    interp_pt(pp.x, pp.y, a0, a1, a2);
    interp_pt(pp.z, pp.w, b0, b1, b2);
    out2[3 * i + 0] = make_float2(a0, a1);
    out2[3 * i + 1] = make_float2(a2, b0);
    out2[3 * i + 2] = make_float2(b1, b2);
}

extern "C" void kernel_launch(void* const* d_in, const int* in_sizes, int n_in,
                              void* d_out, int out_size) {
    const float* xy    = (const float*)d_in[0];
    const float* gamma = (const float*)d_in[1];
    const float* beta  = (const float*)d_in[2];
    const float* w_in  = (const float*)d_in[3];
    const float* b_in  = (const float*)d_in[4];
    const float* w_h   = (const float*)d_in[5];
    const float* b_h   = (const float*)d_in[6];
    const float* w_out = (const float*)d_in[7];
    const float* b_out = (const float*)d_in[8];
    const float* ln_w  = (const float*)d_in[9];
    const float* ln_b  = (const float*)d_in[10];
    float* out = (float*)d_out;
    int n = in_sizes[0] / 2;
    int npair = n / 2;                 // N_POINTS is even

    build_cells<<<40 * 40, 256>>>(gamma, beta, ln_w, ln_b,
                                  w_in, b_in, w_h, b_h, w_out, b_out);

    int main_blocks = (npair + 255) / 256;
    interp_kernel<<<main_blocks, 256>>>((const float4*)xy, (float2*)out, npair);
}